// round 2
// baseline (speedup 1.0000x reference)
#include <cuda_runtime.h>

#define DD      784
#define BB      128
#define CC      10
#define JC      49      // j-chunk
#define NCHUNK  8       // 8*49 = 392 = one j-half
#define JHALF   392
#define XPAD    51      // odd pad -> conflict-free per-lane LDS
#define WROW    20      // floats per (i-pair, j) smem row
#define NCTA    392
#define NK      784     // partial slices = NCTA * 2

// scratch: part[k][c][b], k in [0,784)
__device__ float g_part[NK * CC * BB];

__device__ __forceinline__ unsigned long long pk2(float lo, float hi) {
    unsigned long long r;
    asm("mov.b64 %0, {%1, %2};" : "=l"(r) : "f"(lo), "f"(hi));
    return r;
}
__device__ __forceinline__ unsigned long long dup2(float x) {
    unsigned long long r;
    asm("mov.b64 %0, {%1, %1};" : "=l"(r) : "f"(x));
    return r;
}
__device__ __forceinline__ unsigned long long fma2(unsigned long long a,
                                                   unsigned long long b,
                                                   unsigned long long c) {
    unsigned long long d;
    asm("fma.rn.f32x2 %0, %1, %2, %3;" : "=l"(d) : "l"(a), "l"(b), "l"(c));
    return d;
}
__device__ __forceinline__ void upk2(unsigned long long v, float& lo, float& hi) {
    asm("mov.b64 {%0, %1}, %2;" : "=f"(lo), "=f"(hi) : "l"(v));
}

__global__ __launch_bounds__(256)
void quad_main(const float* __restrict__ X, const float* __restrict__ W) {
    __shared__ __align__(16) float xc[BB * XPAD];       // 26112 B
    __shared__ __align__(16) float wc[2 * JC * WROW];   // 7840 B

    const int tid  = threadIdx.x;
    const int lane = tid & 31;
    const int wid  = tid >> 5;
    const int ig   = wid >> 2;              // i-pair within CTA (0/1)
    const int bq   = wid & 3;
    const int b    = bq * 32 + lane;        // batch owned by this lane
    const int ib   = blockIdx.x >> 1;       // 0..195
    const int jh   = blockIdx.x & 1;        // j-half
    const int i0   = ib * 4 + ig * 2;
    const int i1   = i0 + 1;
    const int jbase = jh * JHALF;

    // acc[0..4]: class-pairs for i0; acc[5..9]: for i1
    unsigned long long acc[10];
    if (jh == 0) {  // fold linear term W1 into init (counted exactly once)
#pragma unroll
        for (int p = 0; p < 5; p++) {
            acc[p]     = pk2(W[i0 * CC + 2 * p], W[i0 * CC + 2 * p + 1]);
            acc[5 + p] = pk2(W[i1 * CC + 2 * p], W[i1 * CC + 2 * p + 1]);
        }
    } else {
#pragma unroll
        for (int p = 0; p < 10; p++) acc[p] = 0ull;
    }

    for (int ch = 0; ch < NCHUNK; ch++) {
        const int jc0 = jbase + ch * JC;

        // stage x chunk: xc[r][off] = X[r][jc0+off]
        for (int g = tid; g < BB * JC; g += 256) {
            int r = g / JC;
            int off = g - r * JC;
            xc[r * XPAD + off] = X[r * DD + jc0 + off];
        }
        // stage W2 chunk rows: [i0 c0..c9 | i1 c0..c9] per (ig, j)
        for (int g = tid; g < 2 * JC * CC; g += 256) {
            int igg = g / (JC * CC);
            int rem = g - igg * (JC * CC);
            int j   = rem / CC;
            int p   = rem - j * CC;
            int sub = p / 5;
            int pp  = p - sub * 5;
            int irow = ib * 4 + igg * 2 + sub;
            const float2 v =
                *(const float2*)(W + (((irow + 1) * DD + (jc0 + j)) * CC + pp * 2));
            *(float2*)(wc + (igg * JC + j) * WROW + p * 2) = v;
        }
        __syncthreads();

        const float* xr = xc + b * XPAD;
        const float* wr = wc + (ig * JC) * WROW;
#pragma unroll 1
        for (int j = 0; j < JC; j++) {
            const unsigned long long x2 = dup2(xr[j]);
            const ulonglong2* wp = (const ulonglong2*)(wr + j * WROW);
            ulonglong2 w0 = wp[0];
            ulonglong2 w1 = wp[1];
            ulonglong2 w2 = wp[2];
            ulonglong2 w3 = wp[3];
            ulonglong2 w4 = wp[4];
            acc[0] = fma2(x2, w0.x, acc[0]);
            acc[1] = fma2(x2, w0.y, acc[1]);
            acc[2] = fma2(x2, w1.x, acc[2]);
            acc[3] = fma2(x2, w1.y, acc[3]);
            acc[4] = fma2(x2, w2.x, acc[4]);
            acc[5] = fma2(x2, w2.y, acc[5]);
            acc[6] = fma2(x2, w3.x, acc[6]);
            acc[7] = fma2(x2, w3.y, acc[7]);
            acc[8] = fma2(x2, w4.x, acc[8]);
            acc[9] = fma2(x2, w4.y, acc[9]);
        }
        __syncthreads();
    }

    // contribution[b,c] = x[b,i0]*accA[c] + x[b,i1]*accB[c]
    const unsigned long long xA = dup2(X[b * DD + i0]);
    const unsigned long long xB = dup2(X[b * DD + i1]);
    const int k = blockIdx.x * 2 + ig;
#pragma unroll
    for (int p = 0; p < 5; p++) {
        unsigned long long z = fma2(xB, acc[5 + p], 0ull);
        z = fma2(xA, acc[p], z);
        float lo, hi;
        upk2(z, lo, hi);
        g_part[(k * CC + 2 * p) * BB + b]     = lo;  // coalesced per warp
        g_part[(k * CC + 2 * p + 1) * BB + b] = hi;
    }
}

// column-sum over k + bias. grid 10 (c), block 512 = (kg 0..3) x (b 0..127)
__global__ __launch_bounds__(512)
void quad_reduce(const float* __restrict__ bias, float* __restrict__ out) {
    __shared__ float sm[512];
    const int c  = blockIdx.x;
    const int t  = threadIdx.x;
    const int b  = t & 127;
    const int kg = t >> 7;

    float s = 0.f;
#pragma unroll 4
    for (int m = 0; m < NK / 4; m++) {
        int k = kg + 4 * m;
        s += g_part[(k * CC + c) * BB + b];   // coalesced: 128 consecutive floats
    }
    sm[t] = s;
    __syncthreads();
    if (kg == 0) {
        float tot = sm[b] + sm[128 + b] + sm[256 + b] + sm[384 + b] + bias[c];
        out[b * CC + c] = tot;
    }
}

extern "C" void kernel_launch(void* const* d_in, const int* in_sizes, int n_in,
                              void* d_out, int out_size) {
    const float* X    = (const float*)d_in[0];  // [128,28,28]
    const float* W    = (const float*)d_in[1];  // [615440,10]
    const float* bias = (const float*)d_in[2];  // [10]
    float* out        = (float*)d_out;          // [128,10]
    (void)in_sizes; (void)n_in; (void)out_size;

    quad_main<<<NCTA, 256>>>(X, W);
    quad_reduce<<<CC, 512>>>(bias, out);
}

// round 3
// speedup vs baseline: 1.0350x; 1.0350x over previous
#include <cuda_runtime.h>

#define DD 784
#define CC 10
#define BBATCH 128
#define JC 112
#define NCHUNK 7
#define NJS 7          // 112/16 j-steps per chunk

typedef unsigned long long ull;

// scratch: g_part[i][c][b]  (784*10*128 floats = 4.01 MB)
__device__ float g_part[DD * CC * BBATCH];
__device__ float g_red[CC * 8 * BBATCH];

__device__ __forceinline__ ull pk2(float lo, float hi) {
    ull r; asm("mov.b64 %0, {%1, %2};" : "=l"(r) : "f"(lo), "f"(hi)); return r;
}
__device__ __forceinline__ ull dup2(float x) {
    ull r; asm("mov.b64 %0, {%1, %1};" : "=l"(r) : "f"(x)); return r;
}
__device__ __forceinline__ ull fma2(ull a, ull b, ull c) {
    ull d; asm("fma.rn.f32x2 %0, %1, %2, %3;" : "=l"(d) : "l"(a), "l"(b), "l"(c)); return d;
}
__device__ __forceinline__ ull add2(ull a, ull b) {
    ull d; asm("add.rn.f32x2 %0, %1, %2;" : "=l"(d) : "l"(a), "l"(b)); return d;
}
__device__ __forceinline__ ull mul2(ull a, ull b) {
    ull d; asm("mul.rn.f32x2 %0, %1, %2;" : "=l"(d) : "l"(a), "l"(b)); return d;
}
__device__ __forceinline__ ull f2u(float2 v) {
    ull r; asm("mov.b64 %0, {%1, %2};" : "=l"(r) : "f"(v.x), "f"(v.y)); return r;
}
__device__ __forceinline__ float2 u2f(ull v) {
    float2 o; asm("mov.b64 {%0, %1}, %2;" : "=f"(o.x), "=f"(o.y) : "l"(v)); return o;
}

// CTA = 256 thr = 8 warps = 2 i  x  4 batch-groups(16b each) -> 64 batches.
// grid 784 = 392 i-pairs x 2 batch-halves.
// Lane = (jo 0..15, h 0..1): jo = parallel j offset, h picks 4 of the warp's
// 8 batch-pairs. acc[c][q] is f32x2 over a batch pair.
__global__ __launch_bounds__(256, 2)
void quad_main(const float* __restrict__ X, const float* __restrict__ W) {
    __shared__ float2 xt2[JC * 32];        // swizzled x pair tile, 28672 B
    __shared__ float  wt[2 * CC * JC];     // W rows transposed [i][c][j], 8960 B

    const int tid  = threadIdx.x;
    const int lane = tid & 31;
    const int wid  = tid >> 5;
    const int i_sub = wid >> 2;            // 0..1
    const int bg    = wid & 3;             // 0..3
    const int jo    = lane & 15;
    const int h     = lane >> 4;
    const int ip    = blockIdx.x >> 1;     // 0..391
    const int bh    = blockIdx.x & 1;      // batch half
    const int i     = ip * 2 + i_sub;      // 0..783
    const int bp0   = bg * 8 + h * 4;      // local batch-pair base (0..31)

    // producer assignment (224 active threads)
    const int pj = tid % JC;
    const int pb = tid / JC;               // 0..1 valid when tid < 224

    ull acc[CC][4];
#pragma unroll
    for (int c = 0; c < CC; c++)
#pragma unroll
        for (int q = 0; q < 4; q++) acc[c][q] = 0ull;

    for (int ch = 0; ch < NCHUNK; ch++) {
        const int jc0 = ch * JC;

        // stage x pairs: xt2[j][swz(bpl)] = (X[b0][jc0+j], X[b0+1][jc0+j])
        if (tid < 224) {
#pragma unroll
            for (int bpl = pb; bpl < 32; bpl += 2) {
                int b0 = (bh * 32 + bpl) * 2;
                float a = X[b0 * DD + jc0 + pj];
                float b = X[(b0 + 1) * DD + jc0 + pj];
                xt2[pj * 32 + (bpl ^ (pj & 15))] = make_float2(a, b);
            }
        }
        // stage W rows transposed: wt[isub][c][j] = W2[i, jc0+j, c]
        for (int g = tid; g < 2 * CC * JC; g += 256) {
            int isub2 = g / (CC * JC);
            int r     = g - isub2 * (CC * JC);
            int c     = r % CC;
            int jj    = r / CC;
            wt[isub2 * (CC * JC) + c * JC + jj] =
                W[((ip * 2 + isub2 + 1) * DD + jc0 + jj) * CC + c];
        }
        __syncthreads();

        const float* wrow = wt + i_sub * (CC * JC);
#pragma unroll 1
        for (int js = 0; js < NJS; js++) {
            const int jl = js * 16 + jo;
            const int m  = jl & 15;
            const float2* xr = xt2 + jl * 32;
            ull x0 = f2u(xr[(bp0 + 0) ^ m]);
            ull x1 = f2u(xr[(bp0 + 1) ^ m]);
            ull x2 = f2u(xr[(bp0 + 2) ^ m]);
            ull x3 = f2u(xr[(bp0 + 3) ^ m]);
            const float* wp = wrow + jl;
#pragma unroll
            for (int c = 0; c < CC; c++) {
                ull wd = dup2(wp[c * JC]);
                acc[c][0] = fma2(wd, x0, acc[c][0]);
                acc[c][1] = fma2(wd, x1, acc[c][1]);
                acc[c][2] = fma2(wd, x2, acc[c][2]);
                acc[c][3] = fma2(wd, x3, acc[c][3]);
            }
        }
        __syncthreads();
    }

    // butterfly-sum over the 16 jo lanes (bits 0..3); h bit untouched
#pragma unroll
    for (int msk = 1; msk <= 8; msk <<= 1) {
#pragma unroll
        for (int c = 0; c < CC; c++)
#pragma unroll
            for (int q = 0; q < 4; q++)
                acc[c][q] = add2(acc[c][q],
                                 __shfl_xor_sync(0xffffffffu, acc[c][q], msk));
    }

    if (jo == 0) {
        // epilogue: (G + W1) * x[b,i] -> scratch
        ull xp[4];
#pragma unroll
        for (int q = 0; q < 4; q++) {
            int b0 = (bh * 32 + bp0 + q) * 2;
            xp[q] = pk2(X[b0 * DD + i], X[(b0 + 1) * DD + i]);
        }
#pragma unroll
        for (int c = 0; c < CC; c++) {
            ull w1 = dup2(W[i * CC + c]);
            float2* gp = (float2*)(g_part + (i * CC + c) * BBATCH);
#pragma unroll
            for (int q = 0; q < 4; q++) {
                ull s = add2(acc[c][q], w1);
                gp[bh * 32 + bp0 + q] = u2f(mul2(xp[q], s));
            }
        }
    }
}

// stage 1: sum 98 i's per (c, iseg). grid 80 = 10c x 8 iseg, block 128 (b)
__global__ __launch_bounds__(128)
void quad_reduce1() {
    const int c    = blockIdx.x >> 3;
    const int iseg = blockIdx.x & 7;
    const int b    = threadIdx.x;
    float s = 0.f;
#pragma unroll 7
    for (int m = 0; m < 98; m++) {
        int i = iseg * 98 + m;
        s += g_part[(i * CC + c) * BBATCH + b];
    }
    g_red[(c * 8 + iseg) * BBATCH + b] = s;
}

// stage 2: sum 8 segments + bias. grid 10, block 128
__global__ __launch_bounds__(128)
void quad_reduce2(const float* __restrict__ bias, float* __restrict__ out) {
    const int c = blockIdx.x;
    const int b = threadIdx.x;
    float s = bias[c];
#pragma unroll
    for (int k = 0; k < 8; k++) s += g_red[(c * 8 + k) * BBATCH + b];
    out[b * CC + c] = s;
}

extern "C" void kernel_launch(void* const* d_in, const int* in_sizes, int n_in,
                              void* d_out, int out_size) {
    const float* X    = (const float*)d_in[0];  // [128,28,28]
    const float* W    = (const float*)d_in[1];  // [615440,10]
    const float* bias = (const float*)d_in[2];  // [10]
    float* out        = (float*)d_out;          // [128,10]
    (void)in_sizes; (void)n_in; (void)out_size;

    quad_main<<<784, 256>>>(X, W);
    quad_reduce1<<<80, 128>>>();
    quad_reduce2<<<10, 128>>>(bias, out);
}

// round 5
// speedup vs baseline: 2.5476x; 2.4615x over previous
#include <cuda_runtime.h>
#include <cuda_bf16.h>
#include <cstdint>

#define DD    784
#define CC    10
#define NTOT  7840
#define NBC   64
#define GRIDM 123
#define NCHN  13
#define PITCH 144      // bytes per tile row (72 bf16)

#define TA_SZ 36864    // [2 split][128][72] bf16
#define TB_SZ 18432    // [2 split][64][72] bf16
#define RB_SZ 20480    // raw W chunk (<= 8 i-rows * 640 floats)
#define OFF_TA0 0
#define OFF_TA1 36864
#define OFF_TB0 73728
#define OFF_TB1 92160
#define OFF_RB0 110592
#define OFF_RB1 131072
#define OFF_BNC 151552
#define SMEM_TOTAL 185344

__device__ __align__(16) unsigned char g_A[NCHN * TA_SZ];
__device__ float g_part[GRIDM * 2 * 128 * CC];

__device__ __forceinline__ uint32_t smem_u32(const void* p) {
    uint32_t a;
    asm("{ .reg .u64 t; cvta.to.shared.u64 t, %1; cvt.u32.u64 %0, t; }" : "=r"(a) : "l"(p));
    return a;
}
#define CP16(dst, src) \
    asm volatile("cp.async.cg.shared.global [%0], [%1], 16;" :: "r"(dst), "l"(src) : "memory")
#define CP_COMMIT() asm volatile("cp.async.commit_group;" ::: "memory")
#define CP_WAIT0()  asm volatile("cp.async.wait_group 0;" ::: "memory")
#define LDSM4(r, addr) \
    asm volatile("ldmatrix.sync.aligned.m8n8.x4.shared.b16 {%0,%1,%2,%3}, [%4];" \
        : "=r"((r)[0]), "=r"((r)[1]), "=r"((r)[2]), "=r"((r)[3]) : "r"(addr))
#define MMA_BF16(d, a, br0, br1) \
    asm volatile("mma.sync.aligned.m16n8k16.row.col.f32.bf16.bf16.f32 " \
        "{%0,%1,%2,%3}, {%4,%5,%6,%7}, {%8,%9}, {%0,%1,%2,%3};" \
        : "+f"((d)[0]), "+f"((d)[1]), "+f"((d)[2]), "+f"((d)[3]) \
        : "r"((a)[0]), "r"((a)[1]), "r"((a)[2]), "r"((a)[3]), "r"(br0), "r"(br1))

// ---------- prep: X -> bf16 hi/lo padded tile image per k-chunk ----------
__global__ __launch_bounds__(256)
void prep_a(const float* __restrict__ X) {
    int flat = blockIdx.x * 256 + threadIdx.x;   // 13*128*16 = 26624
    int ch  = flat >> 11;
    int rem = flat & 2047;
    int b   = rem >> 4;
    int k   = (rem & 15) * 4;
    int j   = ch * 64 + k;
    float f[4] = {0.f, 0.f, 0.f, 0.f};
    if (j < DD) {
        float4 v = *(const float4*)(X + b * DD + j);
        f[0] = v.x; f[1] = v.y; f[2] = v.z; f[3] = v.w;
    }
    __nv_bfloat16 h[4], l[4];
#pragma unroll
    for (int e = 0; e < 4; e++) {
        h[e] = __float2bfloat16(f[e]);
        l[e] = __float2bfloat16(f[e] - __bfloat162float(h[e]));
    }
    unsigned char* base = g_A + ch * TA_SZ + b * PITCH + k * 2;
    *(uint2*)(base)         = *(uint2*)h;
    *(uint2*)(base + 18432) = *(uint2*)l;
}

// ---------- main ----------
__global__ __launch_bounds__(256, 1)
void mma_main(const float* __restrict__ X, const float* __restrict__ W) {
    extern __shared__ __align__(16) unsigned char smem[];
    const uint32_t sb = smem_u32(smem);
    const int tid = threadIdx.x, lane = tid & 31, wid = tid >> 5;
    const int bx = blockIdx.x;
    const int n0 = bx * NBC;
    const int i0 = n0 / 10;
    int ihi = (n0 + NBC - 1) / 10; if (ihi > DD - 1) ihi = DD - 1;
    const int ni = ihi - i0 + 1;                 // <= 8

    const int wm = wid >> 1, wn = wid & 1;
    const int m_base = wm * 32, n_base = wn * 32;
    const int rsel = (lane & 7) + ((lane >> 3) & 1) * 8;
    const int k8b  = ((lane >> 4) * 8) * 2;      // byte offset of k-half
    int aoff[2], boff[2];
#pragma unroll
    for (int q = 0; q < 2; q++) {
        aoff[q] = (m_base + q * 16 + rsel) * PITCH + k8b;
        boff[q] = (n_base + q * 16 + rsel) * PITCH + k8b;
    }

    float acc[2][4][4];
#pragma unroll
    for (int a = 0; a < 2; a++)
#pragma unroll
        for (int b = 0; b < 4; b++)
#pragma unroll
            for (int e = 0; e < 4; e++) acc[a][b][e] = 0.f;

    // ---- staging lambdas (plain code, called with chunk + buf) ----
    auto stage = [&](int cn, int buf) {
        // A tiles: straight copy of prepped image
        const unsigned char* srcA = g_A + cn * TA_SZ;
        uint32_t dstA = sb + (buf ? OFF_TA1 : OFF_TA0);
        for (int u = tid; u < TA_SZ / 16; u += 256)
            CP16(dstA + u * 16, srcA + u * 16);
        // B raw: ni rows of csz*10 floats
        const int csz = (cn == NCHN - 1) ? 16 : 64;
        const int per = csz * 10 / 4;            // 16B units per i-row
        const int j0 = cn * 64;
        uint32_t dstB = sb + (buf ? OFF_RB1 : OFF_RB0);
        for (int u = tid; u < ni * per; u += 256) {
            int ii = u / per, q = u - ii * per;
            const float* src = W + ((size_t)(i0 + ii + 1) * DD + j0) * 10 + q * 4;
            CP16(dstB + (ii * per + q) * 16, src);
        }
    };
    auto convB = [&](int cn, int buf) {
        const int csz = (cn == NCHN - 1) ? 16 : 64;
        const float* rb = (const float*)(smem + (buf ? OFF_RB1 : OFF_RB0));
        unsigned char* tb = smem + (buf ? OFF_TB1 : OFF_TB0);
        for (int u = tid; u < 64 * (csz / 2); u += 256) {
            int n  = u & 63;
            int kp = u >> 6;
            int k  = kp * 2;
            int ng = n0 + n;
            float v0 = 0.f, v1 = 0.f;
            if (ng < NTOT) {
                int i = ng / 10, c = ng - i * 10, ii = i - i0;
                v0 = rb[(ii * csz + k) * 10 + c];
                v1 = rb[(ii * csz + k + 1) * 10 + c];
            }
            __nv_bfloat162 hp, lp;
            hp.x = __float2bfloat16(v0);
            hp.y = __float2bfloat16(v1);
            lp.x = __float2bfloat16(v0 - __bfloat162float(hp.x));
            lp.y = __float2bfloat16(v1 - __bfloat162float(hp.y));
            *(__nv_bfloat162*)(tb + n * PITCH + k * 2)        = hp;
            *(__nv_bfloat162*)(tb + 9216 + n * PITCH + k * 2) = lp;
        }
    };

    // prologue
    stage(0, 0);
    CP_COMMIT(); CP_WAIT0(); __syncthreads();
    convB(0, 0);
    __syncthreads();

    for (int ch = 0; ch < NCHN; ch++) {
        const int buf = ch & 1, nbuf = buf ^ 1;
        if (ch + 1 < NCHN) stage(ch + 1, nbuf);
        CP_COMMIT();

        const uint32_t tA = sb + (buf ? OFF_TA1 : OFF_TA0);
        const uint32_t tB = sb + (buf ? OFF_TB1 : OFF_TB0);
        const int ks = (ch == NCHN - 1) ? 1 : 4;
        for (int s = 0; s < ks; s++) {
            const int koff = s * 32;             // 16 bf16 = 32 bytes
            uint32_t ah[2][4], al[2][4], bh[2][4], bl[2][4];
#pragma unroll
            for (int q = 0; q < 2; q++) {
                LDSM4(ah[q], tA + aoff[q] + koff);
                LDSM4(al[q], tA + 18432 + aoff[q] + koff);
                LDSM4(bh[q], tB + boff[q] + koff);
                LDSM4(bl[q], tB + 9216 + boff[q] + koff);
            }
#pragma unroll
            for (int mi = 0; mi < 2; mi++)
#pragma unroll
                for (int j = 0; j < 4; j++) {
                    const int nt = j >> 1, pr = j & 1;
                    MMA_BF16(acc[mi][j], ah[mi], bh[nt][pr], bh[nt][pr + 2]);
                    MMA_BF16(acc[mi][j], ah[mi], bl[nt][pr], bl[nt][pr + 2]);
                    MMA_BF16(acc[mi][j], al[mi], bh[nt][pr], bh[nt][pr + 2]);
                }
        }
        CP_WAIT0();
        __syncthreads();
        if (ch + 1 < NCHN) convB(ch + 1, nbuf);
        __syncthreads();
    }

    // ---- epilogue: acc -> bounce -> per-(b,c) partials ----
    float* bnc = (float*)(smem + OFF_BNC);       // [128][66]
    {
        const int r = lane >> 2, cq = (lane & 3) * 2;
#pragma unroll
        for (int mi = 0; mi < 2; mi++)
#pragma unroll
            for (int j = 0; j < 4; j++) {
                int row = m_base + mi * 16 + r;
                int col = n_base + j * 8 + cq;
                *(float2*)(bnc + row * 66 + col)       = make_float2(acc[mi][j][0], acc[mi][j][1]);
                *(float2*)(bnc + (row + 8) * 66 + col) = make_float2(acc[mi][j][2], acc[mi][j][3]);
            }
    }
    __syncthreads();
    {
        const int b = tid >> 1, half = tid & 1;
        const int nw = n0 + half * 32;
        const int i_b = nw / 10, r0 = nw - i_b * 10;
        float tacc[10];
#pragma unroll
        for (int k = 0; k < 10; k++) tacc[k] = 0.f;
#pragma unroll
        for (int nl = 0; nl < 32; nl++) {
            int n = nw + nl;
            if (n < NTOT) {
                int idx = r0 + nl;
                int add = (idx >= 10) + (idx >= 20) + (idx >= 30) + (idx >= 40);
                float xv = X[b * DD + i_b + add];
                float g  = bnc[b * 66 + half * 32 + nl];
                tacc[nl % 10] += xv * (g + W[n]);
            }
        }
        float* seg = g_part + (bx * 2 + half) * 1280 + b * 10;
#pragma unroll
        for (int k = 0; k < 10; k++) {
            int c = r0 + k; if (c >= 10) c -= 10;
            seg[c] = tacc[k];
        }
    }
}

// ---------- reduce ----------
__global__ __launch_bounds__(128)
void reduce_k(const float* __restrict__ bias, float* __restrict__ out) {
    const int c = blockIdx.x, b = threadIdx.x;
    float s0 = 0.f, s1 = 0.f;
    for (int q = 0; q < GRIDM * 2; q += 2) {
        s0 += g_part[q * 1280 + b * 10 + c];
        s1 += g_part[(q + 1) * 1280 + b * 10 + c];
    }
    out[b * 10 + c] = s0 + s1 + bias[c];
}

extern "C" void kernel_launch(void* const* d_in, const int* in_sizes, int n_in,
                              void* d_out, int out_size) {
    const float* X    = (const float*)d_in[0];
    const float* W    = (const float*)d_in[1];
    const float* bias = (const float*)d_in[2];
    float* out        = (float*)d_out;
    (void)in_sizes; (void)n_in; (void)out_size;

    cudaFuncSetAttribute(mma_main, cudaFuncAttributeMaxDynamicSharedMemorySize, SMEM_TOTAL);
    prep_a<<<104, 256>>>(X);
    mma_main<<<GRIDM, 256, SMEM_TOTAL>>>(X, W);
    reduce_k<<<CC, 128>>>(bias, out);
}

// round 6
// speedup vs baseline: 3.0460x; 1.1956x over previous
#include <cuda_runtime.h>
#include <cuda_bf16.h>
#include <cstdint>

#define DD    784
#define CC    10
#define NTOT  7840
#define NBC   64
#define GRIDM 123
#define NCHN  13
#define PITCH 144      // bytes per tile row (72 bf16)

#define TA_SZ 36864    // [2 split][128][72] bf16
#define OFF_TA0 0
#define OFF_TA1 36864
#define OFF_TB0 73728
#define OFF_TB1 92160
#define OFF_RB0 110592
#define OFF_RB1 131072
#define OFF_BNC 151552
#define OFF_MBAR 185344
#define SMEM_TOTAL 185408

__device__ __align__(16) unsigned char g_A[NCHN * TA_SZ];
__device__ float g_part[GRIDM * 2 * 128 * CC];   // [slice][c][b]

__device__ __forceinline__ uint32_t smem_u32(const void* p) {
    uint32_t a;
    asm("{ .reg .u64 t; cvta.to.shared.u64 t, %1; cvt.u32.u64 %0, t; }" : "=r"(a) : "l"(p));
    return a;
}
#define MBAR_INIT(a, n) asm volatile("mbarrier.init.shared.b64 [%0], %1;" :: "r"(a), "r"(n) : "memory")
#define MBAR_EXPECT(a, n) asm volatile("mbarrier.arrive.expect_tx.shared.b64 _, [%0], %1;" :: "r"(a), "r"(n) : "memory")
#define MBAR_WAIT(a, ph) do {                                                   \
    asm volatile("{ .reg .pred P1; WL%=:"                                       \
        " mbarrier.try_wait.parity.acquire.cta.shared::cta.b64 P1, [%0], %1, 0x989680;" \
        " @P1 bra.uni WD%=; bra.uni WL%=; WD%=: }"                              \
        :: "r"(a), "r"(ph) : "memory");                                         \
} while (0)
#define BULK(dst, src, sz, mb) \
    asm volatile("cp.async.bulk.shared::cluster.global.mbarrier::complete_tx::bytes " \
        "[%0], [%1], %2, [%3];" :: "r"(dst), "l"(src), "r"(sz), "r"(mb) : "memory")
#define LDSM4(r, addr) \
    asm volatile("ldmatrix.sync.aligned.m8n8.x4.shared.b16 {%0,%1,%2,%3}, [%4];" \
        : "=r"((r)[0]), "=r"((r)[1]), "=r"((r)[2]), "=r"((r)[3]) : "r"(addr))
#define MMA_BF16(d, a, br0, br1) \
    asm volatile("mma.sync.aligned.m16n8k16.row.col.f32.bf16.bf16.f32 " \
        "{%0,%1,%2,%3}, {%4,%5,%6,%7}, {%8,%9}, {%0,%1,%2,%3};" \
        : "+f"((d)[0]), "+f"((d)[1]), "+f"((d)[2]), "+f"((d)[3]) \
        : "r"((a)[0]), "r"((a)[1]), "r"((a)[2]), "r"((a)[3]), "r"(br0), "r"(br1))

// ---------- prep: X -> bf16 hi/lo padded tile image per k-chunk ----------
__global__ __launch_bounds__(256)
void prep_a(const float* __restrict__ X) {
    int flat = blockIdx.x * 256 + threadIdx.x;   // 13*128*16 = 26624
    int ch  = flat >> 11;
    int rem = flat & 2047;
    int b   = rem >> 4;
    int k   = (rem & 15) * 4;
    int j   = ch * 64 + k;
    float f[4] = {0.f, 0.f, 0.f, 0.f};
    if (j < DD) {
        float4 v = *(const float4*)(X + b * DD + j);
        f[0] = v.x; f[1] = v.y; f[2] = v.z; f[3] = v.w;
    }
    __nv_bfloat16 h[4], l[4];
#pragma unroll
    for (int e = 0; e < 4; e++) {
        h[e] = __float2bfloat16(f[e]);
        l[e] = __float2bfloat16(f[e] - __bfloat162float(h[e]));
    }
    unsigned char* base = g_A + ch * TA_SZ + b * PITCH + k * 2;
    *(uint2*)(base)         = *(uint2*)h;
    *(uint2*)(base + 18432) = *(uint2*)l;
}

// ---------- main ----------
__global__ __launch_bounds__(256, 1)
void mma_main(const float* __restrict__ X, const float* __restrict__ W) {
    extern __shared__ __align__(16) unsigned char smem[];
    const uint32_t sb = smem_u32(smem);
    const int tid = threadIdx.x, lane = tid & 31, wid = tid >> 5;
    const int bx = blockIdx.x;
    const int n0 = bx * NBC;
    const int i0 = n0 / 10;
    int ihi = (n0 + NBC - 1) / 10; if (ihi > DD - 1) ihi = DD - 1;
    const int ni = ihi - i0 + 1;                 // <= 8

    const int wm = wid >> 1, wn = wid & 1;
    const int m_base = wm * 32, n_base = wn * 32;
    const int rsel = (lane & 7) + ((lane >> 3) & 1) * 8;
    const int k8b  = ((lane >> 4) * 8) * 2;
    int aoff[2], boff[2];
#pragma unroll
    for (int q = 0; q < 2; q++) {
        aoff[q] = (m_base + q * 16 + rsel) * PITCH + k8b;
        boff[q] = (n_base + q * 16 + rsel) * PITCH + k8b;
    }

    float acc[2][4][4];
#pragma unroll
    for (int a = 0; a < 2; a++)
#pragma unroll
        for (int b = 0; b < 4; b++)
#pragma unroll
            for (int e = 0; e < 4; e++) acc[a][b][e] = 0.f;

    if (tid == 0) { MBAR_INIT(sb + OFF_MBAR, 1); MBAR_INIT(sb + OFF_MBAR + 8, 1); }
    __syncthreads();

    // issue bulk copies for chunk cn into buffer buf (single thread, ~free)
    auto issue = [&](int cn, int buf) {
        if (tid == 0) {
            const uint32_t mb = sb + OFF_MBAR + buf * 8;
            const int csz = (cn == NCHN - 1) ? 16 : 64;
            const int rowb = csz * 40;           // bytes per i-row of raw W
            MBAR_EXPECT(mb, TA_SZ + ni * rowb);
            BULK(sb + (buf ? OFF_TA1 : OFF_TA0), g_A + cn * TA_SZ, TA_SZ, mb);
            const int j0 = cn * 64;
            const uint32_t dstB = sb + (buf ? OFF_RB1 : OFF_RB0);
            for (int ii = 0; ii < ni; ii++) {
                const float* src = W + ((size_t)(i0 + ii + 1) * DD + j0) * 10;
                BULK(dstB + ii * rowb, src, rowb, mb);
            }
        }
    };
    // transpose/split raw B chunk into bf16 tile
    auto convB = [&](int cn, int buf) {
        const int csz = (cn == NCHN - 1) ? 16 : 64;
        const float* rb = (const float*)(smem + (buf ? OFF_RB1 : OFF_RB0));
        unsigned char* tb = smem + (buf ? OFF_TB1 : OFF_TB0);
        for (int u = tid; u < 64 * (csz / 2); u += 256) {
            int n  = u & 63;
            int kp = u >> 6;
            int k  = kp * 2;
            int ng = n0 + n;
            float v0 = 0.f, v1 = 0.f;
            if (ng < NTOT) {
                int i = ng / 10, c = ng - i * 10, ii = i - i0;
                v0 = rb[(ii * csz + k) * 10 + c];
                v1 = rb[(ii * csz + k + 1) * 10 + c];
            }
            __nv_bfloat162 hp, lp;
            hp.x = __float2bfloat16(v0);
            hp.y = __float2bfloat16(v1);
            lp.x = __float2bfloat16(v0 - __bfloat162float(hp.x));
            lp.y = __float2bfloat16(v1 - __bfloat162float(hp.y));
            *(__nv_bfloat162*)(tb + n * PITCH + k * 2)        = hp;
            *(__nv_bfloat162*)(tb + 9216 + n * PITCH + k * 2) = lp;
        }
    };

    // prologue: chunk 0 -> buf 0
    issue(0, 0);
    MBAR_WAIT(sb + OFF_MBAR, 0);
    __syncthreads();
    convB(0, 0);
    __syncthreads();

    for (int ch = 0; ch < NCHN; ch++) {
        const int buf = ch & 1, nbuf = buf ^ 1;
        if (ch + 1 < NCHN) issue(ch + 1, nbuf);

        const uint32_t tA = sb + (buf ? OFF_TA1 : OFF_TA0);
        const uint32_t tB = sb + (buf ? OFF_TB1 : OFF_TB0);
        const int ks = (ch == NCHN - 1) ? 1 : 4;
        for (int s = 0; s < ks; s++) {
            const int koff = s * 32;
            uint32_t ah[2][4], al[2][4], bh[2][4], bl[2][4];
#pragma unroll
            for (int q = 0; q < 2; q++) {
                LDSM4(ah[q], tA + aoff[q] + koff);
                LDSM4(al[q], tA + 18432 + aoff[q] + koff);
                LDSM4(bh[q], tB + boff[q] + koff);
                LDSM4(bl[q], tB + 9216 + boff[q] + koff);
            }
#pragma unroll
            for (int mi = 0; mi < 2; mi++)
#pragma unroll
                for (int j = 0; j < 4; j++) {
                    const int nt = j >> 1, pr = j & 1;
                    MMA_BF16(acc[mi][j], ah[mi], bh[nt][pr], bh[nt][pr + 2]);
                    MMA_BF16(acc[mi][j], ah[mi], bl[nt][pr], bl[nt][pr + 2]);
                    MMA_BF16(acc[mi][j], al[mi], bh[nt][pr], bh[nt][pr + 2]);
                }
        }
        if (ch + 1 < NCHN) {
            MBAR_WAIT(sb + OFF_MBAR + nbuf * 8, ((ch + 1) >> 1) & 1);
            __syncthreads();
            convB(ch + 1, nbuf);
            __syncthreads();
        }
    }

    // ---- epilogue ----
    float* bnc = (float*)(smem + OFF_BNC);       // [128][66]
    {
        const int r = lane >> 2, cq = (lane & 3) * 2;
#pragma unroll
        for (int mi = 0; mi < 2; mi++)
#pragma unroll
            for (int j = 0; j < 4; j++) {
                int row = m_base + mi * 16 + r;
                int col = n_base + j * 8 + cq;
                *(float2*)(bnc + row * 66 + col)       = make_float2(acc[mi][j][0], acc[mi][j][1]);
                *(float2*)(bnc + (row + 8) * 66 + col) = make_float2(acc[mi][j][2], acc[mi][j][3]);
            }
    }
    __syncthreads();
    {
        const int b = tid >> 1, half = tid & 1;
        const int nw = n0 + half * 32;
        const int i_b = nw / 10, r0 = nw - i_b * 10;
        float tacc[10];
#pragma unroll
        for (int k = 0; k < 10; k++) tacc[k] = 0.f;
#pragma unroll
        for (int nl = 0; nl < 32; nl++) {
            int n = nw + nl;
            if (n < NTOT) {
                int idx = r0 + nl;
                int add = (idx >= 10) + (idx >= 20) + (idx >= 30) + (idx >= 40);
                float xv = X[b * DD + i_b + add];
                float g  = bnc[b * 66 + half * 32 + nl];
                tacc[nl % 10] += xv * (g + W[n]);
            }
        }
        float* seg = g_part + (bx * 2 + half) * 1280;
#pragma unroll
        for (int k = 0; k < 10; k++) {
            int c = r0 + k; if (c >= 10) c -= 10;
            seg[c * 128 + b] = tacc[k];          // [slice][c][b] for coalesced reduce
        }
    }
}

// ---------- reduce: coalesced over b ----------
__global__ __launch_bounds__(128)
void reduce_k(const float* __restrict__ bias, float* __restrict__ out) {
    const int c = blockIdx.x, b = threadIdx.x;
    float s0 = 0.f, s1 = 0.f;
    for (int q = 0; q < GRIDM * 2; q += 2) {
        s0 += g_part[q * 1280 + c * 128 + b];
        s1 += g_part[(q + 1) * 1280 + c * 128 + b];
    }
    out[b * 10 + c] = s0 + s1 + bias[c];
}

extern "C" void kernel_launch(void* const* d_in, const int* in_sizes, int n_in,
                              void* d_out, int out_size) {
    const float* X    = (const float*)d_in[0];
    const float* W    = (const float*)d_in[1];
    const float* bias = (const float*)d_in[2];
    float* out        = (float*)d_out;
    (void)in_sizes; (void)n_in; (void)out_size;

    cudaFuncSetAttribute(mma_main, cudaFuncAttributeMaxDynamicSharedMemorySize, SMEM_TOTAL);
    prep_a<<<104, 256>>>(X);
    mma_main<<<GRIDM, 256, SMEM_TOTAL>>>(X, W);
    reduce_k<<<CC, 128>>>(bias, out);
}